// round 1
// baseline (speedup 1.0000x reference)
#include <cuda_runtime.h>
#include <math.h>

#define NN 50000
#define NE 600000
#define CC 128
#define NLAYERS 15

#define ELU_BLOCKS 200
#define ELU_CHUNK  250           // 200*250 = 50000 exactly
#define SCAN_CHUNK 512
#define SCAN_NCHUNK 98           // 98*512 = 50176 >= 50000

// ---------------- static scratch (no runtime allocation allowed) ----------------
__device__ float g_B0[NN * CC];
__device__ float g_B1[NN * CC];
__device__ float g_HE[NN * CC];
__device__ float g_P [NN * CC];
__device__ float g_partial[ELU_BLOCKS * CC];
__device__ float g_cvec[CC];
__device__ float g_masksum;
__device__ int   g_cnt[NN];
__device__ int   g_rowptr[NN + 1];
__device__ int   g_cursor[NN];
__device__ int   g_ccol[NE];
__device__ float g_cval[NE];
__device__ int   g_chunksum[SCAN_NCHUNK];
__device__ int   g_chunkoff[SCAN_NCHUNK];

// ---------------- small helpers ----------------
__device__ __forceinline__ float elu1(float x) {
    return x > 0.f ? x : (__expf(x) - 1.f);
}

__global__ void zero_int_kernel(int* p, int n) {
    int i = blockIdx.x * blockDim.x + threadIdx.x;
    if (i < n) p[i] = 0;
}

// ---------------- CSR build ----------------
__global__ void hist_kernel(const int* __restrict__ row) {
    int e = blockIdx.x * blockDim.x + threadIdx.x;
    if (e < NE) atomicAdd(&g_cnt[row[e]], 1);
}

__global__ void scan1_kernel() {
    __shared__ int s[SCAN_CHUNK];
    int idx = blockIdx.x * SCAN_CHUNK + threadIdx.x;
    int v = (idx < NN) ? g_cnt[idx] : 0;
    s[threadIdx.x] = v;
    __syncthreads();
    // Hillis-Steele inclusive scan
    for (int off = 1; off < SCAN_CHUNK; off <<= 1) {
        int t = (threadIdx.x >= off) ? s[threadIdx.x - off] : 0;
        __syncthreads();
        s[threadIdx.x] += t;
        __syncthreads();
    }
    if (idx < NN) g_rowptr[idx] = s[threadIdx.x];           // inclusive (temp)
    if (threadIdx.x == SCAN_CHUNK - 1) g_chunksum[blockIdx.x] = s[SCAN_CHUNK - 1];
}

__global__ void scan2_kernel() {
    int run = 0;
    for (int b = 0; b < SCAN_NCHUNK; b++) { g_chunkoff[b] = run; run += g_chunksum[b]; }
    g_rowptr[NN] = run;   // == NE
}

__global__ void scan3_kernel() {
    int idx = blockIdx.x * SCAN_CHUNK + threadIdx.x;
    if (idx < NN)
        g_rowptr[idx] = g_chunkoff[blockIdx.x] + g_rowptr[idx] - g_cnt[idx]; // exclusive
}

__global__ void fill_kernel(const int* __restrict__ row, const int* __restrict__ col,
                            const float* __restrict__ val) {
    int e = blockIdx.x * blockDim.x + threadIdx.x;
    if (e >= NE) return;
    int r = row[e];
    int pos = g_rowptr[r] + atomicAdd(&g_cursor[r], 1);
    g_ccol[pos] = col[e];
    g_cval[pos] = val[e];
}

// ---------------- mask sum (once per replay, deterministic in-block tree) -----------
__global__ void masksum_kernel(const float* __restrict__ mask) {
    __shared__ float s[1024];
    float a = 0.f;
    for (int i = threadIdx.x; i < NN; i += 1024) a += mask[i];
    s[threadIdx.x] = a;
    __syncthreads();
    for (int o = 512; o > 0; o >>= 1) {
        if (threadIdx.x < o) s[threadIdx.x] += s[threadIdx.x + o];
        __syncthreads();
    }
    if (threadIdx.x == 0) g_masksum = s[0];
}

// ---------------- conv1: [N,3] @ [3,128] + b ----------------
__global__ void conv1_kernel(const float* __restrict__ in, const float* __restrict__ W,
                             const float* __restrict__ b, float* __restrict__ X) {
    int t = blockIdx.x * blockDim.x + threadIdx.x;
    if (t >= NN * CC) return;
    int n = t >> 7, c = t & 127;
    float x = in[n * 3 + 0] * W[c] + in[n * 3 + 1] * W[CC + c] + in[n * 3 + 2] * W[2 * CC + c] + b[c];
    X[t] = x;
}

// ---------------- elu (+ optional deterministic per-block mean partials) ------------
template <bool RED>
__global__ void elu_kernel(const float* __restrict__ X, float* __restrict__ HE,
                           const float* __restrict__ mask) {
    int c = threadIdx.x;            // 128 threads = one channel each
    int n0 = blockIdx.x * ELU_CHUNK;
    int n1 = n0 + ELU_CHUNK;
    if (n1 > NN) n1 = NN;
    float acc = 0.f;
    for (int n = n0; n < n1; n++) {
        float h = elu1(X[n * CC + c]);
        HE[n * CC + c] = h;
        if (RED) acc += h * mask[n];
    }
    if (RED) g_partial[blockIdx.x * CC + c] = acc;
}

// ---------------- cvec = b + (mean/masksum) @ W_bot  (odd layers) -------------------
__global__ void cvec_kernel(const float* __restrict__ Wbot, const float* __restrict__ b) {
    __shared__ float m[CC];
    int c = threadIdx.x;
    float s = 0.f;
    for (int bi = 0; bi < ELU_BLOCKS; bi++) s += g_partial[bi * CC + c];
    m[c] = s / g_masksum;
    __syncthreads();
    float acc = b[c];
    for (int k = 0; k < CC; k++) acc += m[k] * Wbot[k * CC + c];
    g_cvec[c] = acc;
}

// ---------------- Laplacian segment-sum via CSR: P[r,:] = sum val * HE[col,:] -------
__global__ void lap_kernel(const float* __restrict__ HE, float* __restrict__ P) {
    int warp = (blockIdx.x * blockDim.x + threadIdx.x) >> 5;
    int lane = threadIdx.x & 31;
    if (warp >= NN) return;
    int s = g_rowptr[warp], e1 = g_rowptr[warp + 1];
    float4 acc = make_float4(0.f, 0.f, 0.f, 0.f);
    for (int e = s; e < e1; e++) {
        int col = g_ccol[e];
        float v = g_cval[e];
        float4 h = *(const float4*)&HE[col * CC + lane * 4];
        acc.x += v * h.x; acc.y += v * h.y; acc.z += v * h.z; acc.w += v * h.w;
    }
    *(float4*)&P[warp * CC + lane * 4] = acc;
}

// ---------------- tiled SGEMM: out[N,128] = A[N,K] @ W[K,128] + bias (+res) ---------
// A columns: k<128 -> A1 (HE); k>=128 -> A2 (P)  (only when CONCAT)
template <int KTOT, bool ADD_RES, bool CONCAT>
__global__ __launch_bounds__(256, 2)
void gemm_kernel(const float* __restrict__ A1, const float* __restrict__ A2,
                 const float* __restrict__ W, const float* __restrict__ bias,
                 const float* res, float* out) {
    __shared__ float As[8][128];
    __shared__ float Bs[8][128];
    const int tid = threadIdx.x;
    const int tx = tid & 15;        // output col group (8 cols each)
    const int ty = tid >> 4;        // output row group (8 rows each)
    const int m0 = blockIdx.x * 128;

    // A load mapping: 2 threads per row, each loads float4 along k
    const int lrow = tid >> 1;
    const int lkq = (tid & 1) * 4;
    const int grow = m0 + lrow;
    const bool rowok = (grow < NN);
    // B load mapping: 32 threads per k-row, each loads float4
    const int bk = tid >> 5;
    const int bc = (tid & 31) * 4;

    float acc[8][8] = {};

    for (int kt = 0; kt < KTOT; kt += 8) {
        float4 av = make_float4(0.f, 0.f, 0.f, 0.f);
        if (rowok) {
            int kk = kt + lkq;
            const float* src;
            if (CONCAT && kk >= 128) src = A2 + (size_t)grow * CC + (kk - 128);
            else                     src = A1 + (size_t)grow * CC + kk;
            av = *(const float4*)src;
        }
        As[lkq + 0][lrow] = av.x;
        As[lkq + 1][lrow] = av.y;
        As[lkq + 2][lrow] = av.z;
        As[lkq + 3][lrow] = av.w;
        *(float4*)&Bs[bk][bc] = *(const float4*)&W[(kt + bk) * CC + bc];
        __syncthreads();
#pragma unroll
        for (int k = 0; k < 8; k++) {
            float a[8], b[8];
            *(float4*)&a[0] = *(const float4*)&As[k][ty * 8];
            *(float4*)&a[4] = *(const float4*)&As[k][ty * 8 + 4];
            *(float4*)&b[0] = *(const float4*)&Bs[k][tx * 8];
            *(float4*)&b[4] = *(const float4*)&Bs[k][tx * 8 + 4];
#pragma unroll
            for (int i = 0; i < 8; i++)
#pragma unroll
                for (int j = 0; j < 8; j++)
                    acc[i][j] += a[i] * b[j];
        }
        __syncthreads();
    }

#pragma unroll
    for (int i = 0; i < 8; i++) {
        int r = m0 + ty * 8 + i;
        if (r >= NN) break;
#pragma unroll
        for (int j = 0; j < 8; j += 4) {
            int c = tx * 8 + j;
            float4 v;
            v.x = acc[i][j + 0] + bias[c + 0];
            v.y = acc[i][j + 1] + bias[c + 1];
            v.z = acc[i][j + 2] + bias[c + 2];
            v.w = acc[i][j + 3] + bias[c + 3];
            if (ADD_RES) {
                float4 rr = *(const float4*)&res[(size_t)r * CC + c];
                v.x += rr.x; v.y += rr.y; v.z += rr.z; v.w += rr.w;
            }
            *(float4*)&out[(size_t)r * CC + c] = v;
        }
    }
}

// ---------------- final: out[n] = elu(X[n,:]) . W2 + b2 + inputs[n,0] ---------------
__global__ void final_kernel(const float* __restrict__ X, const float* __restrict__ W2,
                             const float* __restrict__ b2, const float* __restrict__ in,
                             float* __restrict__ out) {
    int warp = (blockIdx.x * blockDim.x + threadIdx.x) >> 5;
    int lane = threadIdx.x & 31;
    if (warp >= NN) return;
    float4 x = *(const float4*)&X[warp * CC + lane * 4];
    x.x = elu1(x.x); x.y = elu1(x.y); x.z = elu1(x.z); x.w = elu1(x.w);
    float4 w = *(const float4*)&W2[lane * 4];
    float s = x.x * w.x + x.y * w.y + x.z * w.z + x.w * w.w;
#pragma unroll
    for (int o = 16; o > 0; o >>= 1) s += __shfl_down_sync(0xffffffffu, s, o);
    if (lane == 0) out[warp] = s + b2[0] + in[warp * 3];
}

// ---------------- host launch ----------------
extern "C" void kernel_launch(void* const* d_in, const int* in_sizes, int n_in,
                              void* d_out, int out_size) {
    const int*   L_row  = (const int*)d_in[0];
    const int*   L_col  = (const int*)d_in[1];
    const float* L_val  = (const float*)d_in[2];
    const float* mask   = (const float*)d_in[3];
    const float* inputs = (const float*)d_in[4];
    const float* W1     = (const float*)d_in[5];
    const float* b1     = (const float*)d_in[6];
    const float* BW     = (const float*)d_in[7];  // [15][2][256][128]
    const float* Bb     = (const float*)d_in[8];  // [15][2][128]
    const float* W2     = (const float*)d_in[9];
    const float* b2     = (const float*)d_in[10];
    float* out = (float*)d_out;

    float *B0, *B1, *HE, *P, *cvec;
    int *cnt, *cursor;
    cudaGetSymbolAddress((void**)&B0, g_B0);
    cudaGetSymbolAddress((void**)&B1, g_B1);
    cudaGetSymbolAddress((void**)&HE, g_HE);
    cudaGetSymbolAddress((void**)&P,  g_P);
    cudaGetSymbolAddress((void**)&cvec, g_cvec);
    cudaGetSymbolAddress((void**)&cnt, g_cnt);
    cudaGetSymbolAddress((void**)&cursor, g_cursor);

    // ---- CSR build (per replay) ----
    zero_int_kernel<<<(NN + 255) / 256, 256>>>(cnt, NN);
    zero_int_kernel<<<(NN + 255) / 256, 256>>>(cursor, NN);
    hist_kernel<<<(NE + 255) / 256, 256>>>(L_row);
    scan1_kernel<<<SCAN_NCHUNK, SCAN_CHUNK>>>();
    scan2_kernel<<<1, 1>>>();
    scan3_kernel<<<SCAN_NCHUNK, SCAN_CHUNK>>>();
    fill_kernel<<<(NE + 255) / 256, 256>>>(L_row, L_col, L_val);
    masksum_kernel<<<1, 1024>>>(mask);

    // ---- conv1 ----
    conv1_kernel<<<(NN * CC + 255) / 256, 256>>>(inputs, W1, b1, B0);

    const int GEMM_GRID = (NN + 127) / 128;   // 391
    const int LAP_GRID  = (NN * 32 + 255) / 256;

    for (int i = 0; i < NLAYERS; i++) {
        for (int j = 0; j < 2; j++) {
            float* inb  = (j == 0) ? B0 : B1;
            float* outb = (j == 0) ? B1 : B0;
            const float* res = B0;            // only used when j==1
            const float* W = BW + (size_t)(i * 2 + j) * 256 * CC;
            const float* b = Bb + (size_t)(i * 2 + j) * CC;

            if ((i & 1) == 0) {
                // Laplacian layer: out = [elu(x) | L@elu(x)] @ W + b (+res)
                elu_kernel<false><<<ELU_BLOCKS, CC>>>(inb, HE, mask);
                lap_kernel<<<LAP_GRID, 256>>>(HE, P);
                if (j == 1)
                    gemm_kernel<256, true, true><<<GEMM_GRID, 256>>>(HE, P, W, b, res, outb);
                else
                    gemm_kernel<256, false, true><<<GEMM_GRID, 256>>>(HE, P, W, b, nullptr, outb);
            } else {
                // Avg layer: out = elu(x) @ W_top + cvec (+res),
                // cvec = b + mean(elu(x)) @ W_bot  (rank-1 collapse of broadcast prop)
                elu_kernel<true><<<ELU_BLOCKS, CC>>>(inb, HE, mask);
                cvec_kernel<<<1, CC>>>(W + 128 * CC, b);
                if (j == 1)
                    gemm_kernel<128, true, false><<<GEMM_GRID, 256>>>(HE, nullptr, W, cvec, res, outb);
                else
                    gemm_kernel<128, false, false><<<GEMM_GRID, 256>>>(HE, nullptr, W, cvec, nullptr, outb);
            }
        }
    }

    // ---- final conv2 + input residual ----
    final_kernel<<<(NN * 32 + 1023) / 1024, 1024>>>(B0, W2, b2, inputs, out);

    (void)in_sizes; (void)n_in; (void)out_size;
}

// round 3
// speedup vs baseline: 1.4091x; 1.4091x over previous
#include <cuda_runtime.h>
#include <cuda_bf16.h>
#include <math.h>
#include <stdint.h>

#define NN 50000
#define NE 600000
#define CC 128
#define NLAYERS 15
#define NSTEPS 30

#define ELU_BLOCKS 200
#define ELU_CHUNK  250
#define SCAN_CHUNK 512
#define SCAN_NCHUNK 98

// ---------------- static scratch ----------------
__device__ float g_B0[NN * CC];
__device__ float g_B1[NN * CC];
__device__ float g_HE[NN * CC];
__device__ float g_P [NN * CC];
__device__ float g_partial[ELU_BLOCKS * CC];
__device__ float g_cvec[CC];
__device__ float g_masksum;
__device__ int   g_cnt[NN];
__device__ int   g_rowptr[NN + 1];
__device__ int   g_cursor[NN];
__device__ int   g_ccol[NE];
__device__ float g_cval[NE];
__device__ int   g_chunksum[SCAN_NCHUNK];
__device__ int   g_chunkoff[SCAN_NCHUNK];
// weight bf16 hi/lo images: [step 30][n 128][k 256]
__device__ __nv_bfloat16 g_Wh[NSTEPS * 128 * 256];
__device__ __nv_bfloat16 g_Wl[NSTEPS * 128 * 256];

// ---------------- helpers ----------------
__device__ __forceinline__ uint32_t smem_u32(const void* p) {
    uint32_t a;
    asm("{ .reg .u64 t; cvta.to.shared.u64 t, %1; cvt.u32.u64 %0, t; }" : "=r"(a) : "l"(p));
    return a;
}
__device__ __forceinline__ float elu1(float x) {
    return x > 0.f ? x : (__expf(x) - 1.f);
}
__device__ __forceinline__ unsigned short bfbits(float x) {
    return __bfloat16_as_ushort(__float2bfloat16_rn(x));
}
__device__ __forceinline__ void ldsm_x4(uint32_t* r, uint32_t addr) {
    asm volatile("ldmatrix.sync.aligned.m8n8.x4.shared.b16 {%0,%1,%2,%3}, [%4];"
                 : "=r"(r[0]), "=r"(r[1]), "=r"(r[2]), "=r"(r[3]) : "r"(addr));
}
__device__ __forceinline__ void mma16816(float* d, const uint32_t* a, const uint32_t* b) {
    asm volatile("mma.sync.aligned.m16n8k16.row.col.f32.bf16.bf16.f32 "
                 "{%0,%1,%2,%3}, {%4,%5,%6,%7}, {%8,%9}, {%0,%1,%2,%3};"
                 : "+f"(d[0]), "+f"(d[1]), "+f"(d[2]), "+f"(d[3])
                 : "r"(a[0]), "r"(a[1]), "r"(a[2]), "r"(a[3]), "r"(b[0]), "r"(b[1]));
}

// ---------------- CSR build ----------------
__global__ void zero_int_kernel(int* p, int n) {
    int i = blockIdx.x * blockDim.x + threadIdx.x;
    if (i < n) p[i] = 0;
}
__global__ void hist_kernel(const int* __restrict__ row) {
    int e = blockIdx.x * blockDim.x + threadIdx.x;
    if (e < NE) atomicAdd(&g_cnt[row[e]], 1);
}
__global__ void scan1_kernel() {
    __shared__ int s[SCAN_CHUNK];
    int idx = blockIdx.x * SCAN_CHUNK + threadIdx.x;
    int v = (idx < NN) ? g_cnt[idx] : 0;
    s[threadIdx.x] = v;
    __syncthreads();
    for (int off = 1; off < SCAN_CHUNK; off <<= 1) {
        int t = (threadIdx.x >= off) ? s[threadIdx.x - off] : 0;
        __syncthreads();
        s[threadIdx.x] += t;
        __syncthreads();
    }
    if (idx < NN) g_rowptr[idx] = s[threadIdx.x];
    if (threadIdx.x == SCAN_CHUNK - 1) g_chunksum[blockIdx.x] = s[SCAN_CHUNK - 1];
}
__global__ void scan2_kernel() {
    int run = 0;
    for (int b = 0; b < SCAN_NCHUNK; b++) { g_chunkoff[b] = run; run += g_chunksum[b]; }
    g_rowptr[NN] = run;
}
__global__ void scan3_kernel() {
    int idx = blockIdx.x * SCAN_CHUNK + threadIdx.x;
    if (idx < NN)
        g_rowptr[idx] = g_chunkoff[blockIdx.x] + g_rowptr[idx] - g_cnt[idx];
}
__global__ void fill_kernel(const int* __restrict__ row, const int* __restrict__ col,
                            const float* __restrict__ val) {
    int e = blockIdx.x * blockDim.x + threadIdx.x;
    if (e >= NE) return;
    int r = row[e];
    int pos = g_rowptr[r] + atomicAdd(&g_cursor[r], 1);
    g_ccol[pos] = col[e];
    g_cval[pos] = val[e];
}
__global__ void masksum_kernel(const float* __restrict__ mask) {
    __shared__ float s[1024];
    float a = 0.f;
    for (int i = threadIdx.x; i < NN; i += 1024) a += mask[i];
    s[threadIdx.x] = a;
    __syncthreads();
    for (int o = 512; o > 0; o >>= 1) {
        if (threadIdx.x < o) s[threadIdx.x] += s[threadIdx.x + o];
        __syncthreads();
    }
    if (threadIdx.x == 0) g_masksum = s[0];
}

// ---------------- weight prep: transpose + bf16 hi/lo split ----------------
__global__ void wprep_kernel(const float* __restrict__ BW) {
    int t = blockIdx.x * blockDim.x + threadIdx.x;
    if (t >= NSTEPS * 128 * 256) return;
    int step = t >> 15;             // /(128*256)
    int r = t & 32767;
    int n = r >> 8;
    int k = r & 255;
    float x = BW[(size_t)step * 256 * 128 + (size_t)k * 128 + n];
    __nv_bfloat16 h = __float2bfloat16_rn(x);
    float lo = x - __bfloat162float(h);
    g_Wh[t] = h;
    g_Wl[t] = __float2bfloat16_rn(lo);
}

// ---------------- conv1 ----------------
__global__ void conv1_kernel(const float* __restrict__ in, const float* __restrict__ W,
                             const float* __restrict__ b, float* __restrict__ X) {
    int t = blockIdx.x * blockDim.x + threadIdx.x;
    if (t >= NN * CC) return;
    int n = t >> 7, c = t & 127;
    X[t] = in[n * 3 + 0] * W[c] + in[n * 3 + 1] * W[CC + c] + in[n * 3 + 2] * W[2 * CC + c] + b[c];
}

// ---------------- elu (+ optional mean partials) ----------------
template <bool RED>
__global__ void elu_kernel(const float* __restrict__ X, float* __restrict__ HE,
                           const float* __restrict__ mask) {
    int c = threadIdx.x;
    int n0 = blockIdx.x * ELU_CHUNK;
    int n1 = n0 + ELU_CHUNK;
    if (n1 > NN) n1 = NN;
    float acc = 0.f;
    for (int n = n0; n < n1; n++) {
        float h = elu1(X[n * CC + c]);
        HE[n * CC + c] = h;
        if (RED) acc += h * mask[n];
    }
    if (RED) g_partial[blockIdx.x * CC + c] = acc;
}

// ---------------- cvec = b + mean(elu(x)) @ W_bot ----------------
__global__ void cvec_kernel(const float* __restrict__ Wbot, const float* __restrict__ b) {
    __shared__ float m[CC];
    int c = threadIdx.x;
    float s = 0.f;
    for (int bi = 0; bi < ELU_BLOCKS; bi++) s += g_partial[bi * CC + c];
    m[c] = s / g_masksum;
    __syncthreads();
    float acc = b[c];
    for (int k = 0; k < CC; k++) acc += m[k] * Wbot[k * CC + c];
    g_cvec[c] = acc;
}

// ---------------- Laplacian segment-sum via CSR ----------------
__global__ void lap_kernel(const float* __restrict__ HE, float* __restrict__ P) {
    int warp = (blockIdx.x * blockDim.x + threadIdx.x) >> 5;
    int lane = threadIdx.x & 31;
    if (warp >= NN) return;
    int s = g_rowptr[warp], e1 = g_rowptr[warp + 1];
    float4 acc = make_float4(0.f, 0.f, 0.f, 0.f);
    for (int e = s; e < e1; e++) {
        int col = g_ccol[e];
        float v = g_cval[e];
        float4 h = *(const float4*)&HE[col * CC + lane * 4];
        acc.x += v * h.x; acc.y += v * h.y; acc.z += v * h.z; acc.w += v * h.w;
    }
    *(float4*)&P[warp * CC + lane * 4] = acc;
}

// ---------------- HMMA GEMM: out[N,128] = A[N,K]@W[K,128] + bias (+res) -------------
// Split precision: out = Ah@Wh + Ah@Wl + Al@Wh (fp32 accumulate).
// NCH: number of 128-wide K chunks (2 for lap layers, 1 for avg).
// CONCAT: chunk 1 comes from A2 instead of A1.
#define STRD 136                        // bf16 SMEM row stride (ldmatrix conflict-free)
#define ASZ  (128 * STRD * 2)           // 34816 bytes per array
#define SMTOT (4 * ASZ)                 // AH AL BH BL

template <int NCH, bool ADD_RES, bool CONCAT>
__global__ __launch_bounds__(256, 1)
void gemm_mma(const float* __restrict__ A1, const float* __restrict__ A2,
              const __nv_bfloat16* __restrict__ Wh, const __nv_bfloat16* __restrict__ Wl,
              const float* __restrict__ bias, const float* __restrict__ res,
              float* __restrict__ out) {
    extern __shared__ char smem[];
    char* AH = smem;
    char* AL = smem + ASZ;
    char* BH = smem + 2 * ASZ;
    char* BL = smem + 3 * ASZ;
    const uint32_t sb = smem_u32(smem);

    const int tid = threadIdx.x;
    const int wid = tid >> 5, lane = tid & 31;
    const int wm = wid & 3, wn = wid >> 2;      // warp grid 4 x 2, warp tile 32x64
    const int m0 = blockIdx.x * 128;
    const int gid = lane >> 2, tid4 = lane & 3;

    float acc[2][8][4] = {};

    // staging mapping: 2 threads per row, 64 cols each
    const int frow = tid >> 1;
    const int fcol = (tid & 1) * 64;
    const bool rowok = (m0 + frow) < NN;

    // ldmatrix per-lane base addresses (byte)
    const uint32_t aBase = sb +
        (uint32_t)(((wm * 32 + (lane & 15)) * STRD + (lane >> 4) * 8) * 2);
    const uint32_t bBase = sb + 2 * ASZ +
        (uint32_t)(((wn * 64 + (lane & 7) + ((lane >> 4) * 8)) * STRD + ((lane >> 3) & 1) * 8) * 2);

#pragma unroll
    for (int kc = 0; kc < NCH; kc++) {
        if (kc > 0) __syncthreads();
        // ---- stage A (fp32 -> bf16 hi/lo) ----
        {
            const float* Ag = (CONCAT && kc == 1) ? A2 : A1;
            const float* ap = Ag + (size_t)(m0 + frow) * CC + fcol;
            char* dh = AH + (frow * STRD + fcol) * 2;
            char* dl = AL + (frow * STRD + fcol) * 2;
#pragma unroll
            for (int q = 0; q < 16; q++) {
                float4 v = rowok ? *(const float4*)(ap + q * 4) : make_float4(0.f, 0.f, 0.f, 0.f);
                unsigned short hx = bfbits(v.x), hy = bfbits(v.y), hz = bfbits(v.z), hw = bfbits(v.w);
                float lx = v.x - __bfloat162float(__ushort_as_bfloat16(hx));
                float ly = v.y - __bfloat162float(__ushort_as_bfloat16(hy));
                float lz = v.z - __bfloat162float(__ushort_as_bfloat16(hz));
                float lw = v.w - __bfloat162float(__ushort_as_bfloat16(hw));
                *(uint2*)(dh + q * 8) =
                    make_uint2((uint32_t)hx | ((uint32_t)hy << 16), (uint32_t)hz | ((uint32_t)hw << 16));
                *(uint2*)(dl + q * 8) =
                    make_uint2((uint32_t)bfbits(lx) | ((uint32_t)bfbits(ly) << 16),
                               (uint32_t)bfbits(lz) | ((uint32_t)bfbits(lw) << 16));
            }
        }
        // ---- stage B (copy prepped bf16, add padding) ----
        {
            const __nv_bfloat16* gh = Wh + (size_t)frow * 256 + kc * 128 + fcol;
            const __nv_bfloat16* gl = Wl + (size_t)frow * 256 + kc * 128 + fcol;
            char* dh = BH + (frow * STRD + fcol) * 2;
            char* dl = BL + (frow * STRD + fcol) * 2;
#pragma unroll
            for (int q = 0; q < 8; q++) {
                *(uint4*)(dh + q * 16) = *(const uint4*)((const char*)gh + q * 16);
                *(uint4*)(dl + q * 16) = *(const uint4*)((const char*)gl + q * 16);
            }
        }
        __syncthreads();

        // ---- 8 k16 steps ----
#pragma unroll
        for (int ks = 0; ks < 8; ks++) {
            uint32_t ah[2][4], al[2][4], bh[4][4], bl[4][4];
#pragma unroll
            for (int mf = 0; mf < 2; mf++) {
                uint32_t off = (uint32_t)((mf * 16 * STRD + ks * 16) * 2);
                ldsm_x4(ah[mf], aBase + off);
                ldsm_x4(al[mf], aBase + ASZ + off);
            }
#pragma unroll
            for (int nfp = 0; nfp < 4; nfp++) {
                uint32_t off = (uint32_t)((nfp * 16 * STRD + ks * 16) * 2);
                ldsm_x4(bh[nfp], bBase + off);
                ldsm_x4(bl[nfp], bBase + ASZ + off);
            }
#pragma unroll
            for (int mf = 0; mf < 2; mf++)
#pragma unroll
                for (int nfp = 0; nfp < 4; nfp++)
#pragma unroll
                    for (int h = 0; h < 2; h++) {
                        float* d = acc[mf][nfp * 2 + h];
                        mma16816(d, ah[mf], &bh[nfp][h * 2]);
                        mma16816(d, ah[mf], &bl[nfp][h * 2]);
                        mma16816(d, al[mf], &bh[nfp][h * 2]);
                    }
        }
    }

    // ---- epilogue ----
#pragma unroll
    for (int mf = 0; mf < 2; mf++) {
#pragma unroll
        for (int h = 0; h < 2; h++) {
            int row = m0 + wm * 32 + mf * 16 + gid + h * 8;
            if (row < NN) {
#pragma unroll
                for (int nf = 0; nf < 8; nf++) {
                    int col = wn * 64 + nf * 8 + tid4 * 2;
                    float2 v;
                    v.x = acc[mf][nf][h * 2 + 0] + bias[col];
                    v.y = acc[mf][nf][h * 2 + 1] + bias[col + 1];
                    if (ADD_RES) {
                        float2 rr = *(const float2*)&res[(size_t)row * CC + col];
                        v.x += rr.x; v.y += rr.y;
                    }
                    *(float2*)&out[(size_t)row * CC + col] = v;
                }
            }
        }
    }
}

// ---------------- final: out[n] = elu(X[n,:]) . W2 + b2 + inputs[n,0] ----------------
__global__ void final_kernel(const float* __restrict__ X, const float* __restrict__ W2,
                             const float* __restrict__ b2, const float* __restrict__ in,
                             float* __restrict__ out) {
    int warp = (blockIdx.x * blockDim.x + threadIdx.x) >> 5;
    int lane = threadIdx.x & 31;
    if (warp >= NN) return;
    float4 x = *(const float4*)&X[warp * CC + lane * 4];
    x.x = elu1(x.x); x.y = elu1(x.y); x.z = elu1(x.z); x.w = elu1(x.w);
    float4 w = *(const float4*)&W2[lane * 4];
    float s = x.x * w.x + x.y * w.y + x.z * w.z + x.w * w.w;
#pragma unroll
    for (int o = 16; o > 0; o >>= 1) s += __shfl_down_sync(0xffffffffu, s, o);
    if (lane == 0) out[warp] = s + b2[0] + in[warp * 3];
}

// ---------------- host launch ----------------
extern "C" void kernel_launch(void* const* d_in, const int* in_sizes, int n_in,
                              void* d_out, int out_size) {
    const int*   L_row  = (const int*)d_in[0];
    const int*   L_col  = (const int*)d_in[1];
    const float* L_val  = (const float*)d_in[2];
    const float* mask   = (const float*)d_in[3];
    const float* inputs = (const float*)d_in[4];
    const float* W1     = (const float*)d_in[5];
    const float* b1     = (const float*)d_in[6];
    const float* BW     = (const float*)d_in[7];
    const float* Bb     = (const float*)d_in[8];
    const float* W2     = (const float*)d_in[9];
    const float* b2     = (const float*)d_in[10];
    float* out = (float*)d_out;

    float *B0, *B1, *HE, *P, *cvec;
    __nv_bfloat16 *Wh, *Wl;
    int *cnt, *cursor;
    cudaGetSymbolAddress((void**)&B0, g_B0);
    cudaGetSymbolAddress((void**)&B1, g_B1);
    cudaGetSymbolAddress((void**)&HE, g_HE);
    cudaGetSymbolAddress((void**)&P,  g_P);
    cudaGetSymbolAddress((void**)&cvec, g_cvec);
    cudaGetSymbolAddress((void**)&cnt, g_cnt);
    cudaGetSymbolAddress((void**)&cursor, g_cursor);
    cudaGetSymbolAddress((void**)&Wh, g_Wh);
    cudaGetSymbolAddress((void**)&Wl, g_Wl);

    static bool attr_done = false;
    if (!attr_done) {
        cudaFuncSetAttribute(gemm_mma<2, false, true>,  cudaFuncAttributeMaxDynamicSharedMemorySize, SMTOT);
        cudaFuncSetAttribute(gemm_mma<2, true,  true>,  cudaFuncAttributeMaxDynamicSharedMemorySize, SMTOT);
        cudaFuncSetAttribute(gemm_mma<1, false, false>, cudaFuncAttributeMaxDynamicSharedMemorySize, SMTOT);
        cudaFuncSetAttribute(gemm_mma<1, true,  false>, cudaFuncAttributeMaxDynamicSharedMemorySize, SMTOT);
        attr_done = true;
    }

    // ---- CSR build + weight prep (per replay) ----
    zero_int_kernel<<<(NN + 255) / 256, 256>>>(cnt, NN);
    zero_int_kernel<<<(NN + 255) / 256, 256>>>(cursor, NN);
    hist_kernel<<<(NE + 255) / 256, 256>>>(L_row);
    scan1_kernel<<<SCAN_NCHUNK, SCAN_CHUNK>>>();
    scan2_kernel<<<1, 1>>>();
    scan3_kernel<<<SCAN_NCHUNK, SCAN_CHUNK>>>();
    fill_kernel<<<(NE + 255) / 256, 256>>>(L_row, L_col, L_val);
    masksum_kernel<<<1, 1024>>>(mask);
    wprep_kernel<<<(NSTEPS * 128 * 256 + 255) / 256, 256>>>(BW);

    conv1_kernel<<<(NN * CC + 255) / 256, 256>>>(inputs, W1, b1, B0);

    const int GEMM_GRID = (NN + 127) / 128;   // 391
    const int LAP_GRID  = (NN * 32 + 255) / 256;

    for (int i = 0; i < NLAYERS; i++) {
        for (int j = 0; j < 2; j++) {
            int step = i * 2 + j;
            float* inb  = (j == 0) ? B0 : B1;
            float* outb = (j == 0) ? B1 : B0;
            const float* res = B0;
            const __nv_bfloat16* Whs = Wh + (size_t)step * 128 * 256;
            const __nv_bfloat16* Wls = Wl + (size_t)step * 128 * 256;
            const float* b = Bb + (size_t)step * CC;

            if ((i & 1) == 0) {
                elu_kernel<false><<<ELU_BLOCKS, CC>>>(inb, HE, mask);
                lap_kernel<<<LAP_GRID, 256>>>(HE, P);
                if (j == 1)
                    gemm_mma<2, true,  true><<<GEMM_GRID, 256, SMTOT>>>(HE, P, Whs, Wls, b, res, outb);
                else
                    gemm_mma<2, false, true><<<GEMM_GRID, 256, SMTOT>>>(HE, P, Whs, Wls, b, nullptr, outb);
            } else {
                elu_kernel<true><<<ELU_BLOCKS, CC>>>(inb, HE, mask);
                cvec_kernel<<<1, CC>>>(BW + (size_t)step * 256 * CC + 128 * CC, b);
                if (j == 1)
                    gemm_mma<1, true,  false><<<GEMM_GRID, 256, SMTOT>>>(HE, nullptr, Whs, Wls, cvec, res, outb);
                else
                    gemm_mma<1, false, false><<<GEMM_GRID, 256, SMTOT>>>(HE, nullptr, Whs, Wls, cvec, nullptr, outb);
            }
        }
    }

    final_kernel<<<(NN * 32 + 1023) / 1024, 1024>>>(B0, W2, b2, inputs, out);

    (void)in_sizes; (void)n_in; (void)out_size;
}

// round 4
// speedup vs baseline: 1.8017x; 1.2786x over previous
#include <cuda_runtime.h>
#include <cuda_bf16.h>
#include <math.h>
#include <stdint.h>

#define NN 50000
#define NE 600000
#define CC 128
#define NLAYERS 15
#define NSTEPS 30
#define GGRID 391                 // ceil(NN/128)

#define SCAN_CHUNK 512
#define SCAN_NCHUNK 98

// ---------------- static scratch ----------------
__device__ float g_B0[NN * CC];          // layer-input x (residual source)
__device__ float g_HE[NN * CC];          // elu(x)
__device__ float g_P [NN * CC];          // Laplacian propagate
__device__ float g_partial[GGRID * CC];
__device__ float g_cvec[CC];
__device__ float g_masksum;
__device__ int   g_cnt[NN];
__device__ int   g_rowptr[NN + 1];
__device__ int   g_cursor[NN];
__device__ int   g_ccol[NE];
__device__ float g_cval[NE];
__device__ int   g_chunksum[SCAN_NCHUNK];
// weight bf16 hi/lo images: [step 30][n 128][k 256]
__device__ __nv_bfloat16 g_Wh[NSTEPS * 128 * 256];
__device__ __nv_bfloat16 g_Wl[NSTEPS * 128 * 256];

// ---------------- helpers ----------------
__device__ __forceinline__ uint32_t smem_u32(const void* p) {
    uint32_t a;
    asm("{ .reg .u64 t; cvta.to.shared.u64 t, %1; cvt.u32.u64 %0, t; }" : "=r"(a) : "l"(p));
    return a;
}
__device__ __forceinline__ float elu1(float x) {
    return x > 0.f ? x : (__expf(x) - 1.f);
}
__device__ __forceinline__ unsigned short bfbits(float x) {
    return __bfloat16_as_ushort(__float2bfloat16_rn(x));
}
__device__ __forceinline__ void ldsm_x4(uint32_t* r, uint32_t addr) {
    asm volatile("ldmatrix.sync.aligned.m8n8.x4.shared.b16 {%0,%1,%2,%3}, [%4];"
                 : "=r"(r[0]), "=r"(r[1]), "=r"(r[2]), "=r"(r[3]) : "r"(addr));
}
__device__ __forceinline__ void mma16816(float* d, const uint32_t* a, const uint32_t* b) {
    asm volatile("mma.sync.aligned.m16n8k16.row.col.f32.bf16.bf16.f32 "
                 "{%0,%1,%2,%3}, {%4,%5,%6,%7}, {%8,%9}, {%0,%1,%2,%3};"
                 : "+f"(d[0]), "+f"(d[1]), "+f"(d[2]), "+f"(d[3])
                 : "r"(a[0]), "r"(a[1]), "r"(a[2]), "r"(a[3]), "r"(b[0]), "r"(b[1]));
}
__device__ __forceinline__ void cp16(uint32_t dst, const void* src) {
    asm volatile("cp.async.cg.shared.global [%0], [%1], 16;" :: "r"(dst), "l"(src));
}
__device__ __forceinline__ void cp_wait() {
    asm volatile("cp.async.commit_group;\n\tcp.async.wait_group 0;" ::: "memory");
}

// ---------------- CSR build ----------------
__global__ void zero2_kernel() {
    int i = blockIdx.x * blockDim.x + threadIdx.x;
    if (i < NN) { g_cnt[i] = 0; g_cursor[i] = 0; }
}
__global__ void hist_kernel(const int* __restrict__ row) {
    int e = blockIdx.x * blockDim.x + threadIdx.x;
    if (e < NE) atomicAdd(&g_cnt[row[e]], 1);
}
__global__ void scan1_kernel() {
    __shared__ int s[SCAN_CHUNK];
    int idx = blockIdx.x * SCAN_CHUNK + threadIdx.x;
    int v = (idx < NN) ? g_cnt[idx] : 0;
    s[threadIdx.x] = v;
    __syncthreads();
    for (int off = 1; off < SCAN_CHUNK; off <<= 1) {
        int t = (threadIdx.x >= off) ? s[threadIdx.x - off] : 0;
        __syncthreads();
        s[threadIdx.x] += t;
        __syncthreads();
    }
    if (idx < NN) g_rowptr[idx] = s[threadIdx.x];
    if (threadIdx.x == SCAN_CHUNK - 1) g_chunksum[blockIdx.x] = s[SCAN_CHUNK - 1];
}
__global__ void scan23_kernel() {
    __shared__ int off;
    if (threadIdx.x == 0) {
        int run = 0;
        for (int q = 0; q < blockIdx.x; q++) run += g_chunksum[q];
        off = run;
        if (blockIdx.x == SCAN_NCHUNK - 1) g_rowptr[NN] = run + g_chunksum[blockIdx.x];
    }
    __syncthreads();
    int idx = blockIdx.x * SCAN_CHUNK + threadIdx.x;
    if (idx < NN)
        g_rowptr[idx] = off + g_rowptr[idx] - g_cnt[idx];
}
__global__ void fill_kernel(const int* __restrict__ row, const int* __restrict__ col,
                            const float* __restrict__ val) {
    int e = blockIdx.x * blockDim.x + threadIdx.x;
    if (e >= NE) return;
    int r = row[e];
    int pos = g_rowptr[r] + atomicAdd(&g_cursor[r], 1);
    g_ccol[pos] = col[e];
    g_cval[pos] = val[e];
}
__global__ void masksum_kernel(const float* __restrict__ mask) {
    __shared__ float s[1024];
    float a = 0.f;
    for (int i = threadIdx.x; i < NN; i += 1024) a += mask[i];
    s[threadIdx.x] = a;
    __syncthreads();
    for (int o = 512; o > 0; o >>= 1) {
        if (threadIdx.x < o) s[threadIdx.x] += s[threadIdx.x + o];
        __syncthreads();
    }
    if (threadIdx.x == 0) g_masksum = s[0];
}

// ---------------- weight prep: transpose + bf16 hi/lo split ----------------
__global__ void wprep_kernel(const float* __restrict__ BW) {
    int t = blockIdx.x * blockDim.x + threadIdx.x;
    if (t >= NSTEPS * 128 * 256) return;
    int step = t >> 15;
    int r = t & 32767;
    int n = r >> 8;
    int k = r & 255;
    float x = BW[(size_t)step * 256 * 128 + (size_t)k * 128 + n];
    __nv_bfloat16 h = __float2bfloat16_rn(x);
    float lo = x - __bfloat162float(h);
    g_Wh[t] = h;
    g_Wl[t] = __float2bfloat16_rn(lo);
}

// ---------------- conv1 (+fused elu) ----------------
__global__ void conv1_kernel(const float* __restrict__ in, const float* __restrict__ W,
                             const float* __restrict__ b, float* __restrict__ X,
                             float* __restrict__ HE) {
    int t = blockIdx.x * blockDim.x + threadIdx.x;
    if (t >= NN * CC) return;
    int n = t >> 7, c = t & 127;
    float x = in[n * 3 + 0] * W[c] + in[n * 3 + 1] * W[CC + c] + in[n * 3 + 2] * W[2 * CC + c] + b[c];
    X[t] = x;
    HE[t] = elu1(x);
}

// ---------------- cvec = b + mean(elu(x)) @ W_bot ----------------
__global__ void cvec_kernel(const float* __restrict__ Wbot, const float* __restrict__ b) {
    __shared__ float m[CC];
    int c = threadIdx.x;
    float s = 0.f;
    for (int bi = 0; bi < GGRID; bi++) s += g_partial[bi * CC + c];
    m[c] = s / g_masksum;
    __syncthreads();
    float acc = b[c];
    for (int k = 0; k < CC; k++) acc += m[k] * Wbot[k * CC + c];
    g_cvec[c] = acc;
}

// ---------------- Laplacian segment-sum via CSR ----------------
__global__ void lap_kernel(const float* __restrict__ HE, float* __restrict__ P) {
    int warp = (blockIdx.x * blockDim.x + threadIdx.x) >> 5;
    int lane = threadIdx.x & 31;
    if (warp >= NN) return;
    int s = g_rowptr[warp], e1 = g_rowptr[warp + 1];
    float4 acc = make_float4(0.f, 0.f, 0.f, 0.f);
    int e = s;
    for (; e + 2 <= e1; e += 2) {
        int c0 = g_ccol[e], c1 = g_ccol[e + 1];
        float v0 = g_cval[e], v1 = g_cval[e + 1];
        float4 h0 = *(const float4*)&HE[(size_t)c0 * CC + lane * 4];
        float4 h1 = *(const float4*)&HE[(size_t)c1 * CC + lane * 4];
        acc.x += v0 * h0.x + v1 * h1.x;
        acc.y += v0 * h0.y + v1 * h1.y;
        acc.z += v0 * h0.z + v1 * h1.z;
        acc.w += v0 * h0.w + v1 * h1.w;
    }
    if (e < e1) {
        int c0 = g_ccol[e];
        float v0 = g_cval[e];
        float4 h0 = *(const float4*)&HE[(size_t)c0 * CC + lane * 4];
        acc.x += v0 * h0.x; acc.y += v0 * h0.y; acc.z += v0 * h0.z; acc.w += v0 * h0.w;
    }
    *(float4*)&P[(size_t)warp * CC + lane * 4] = acc;
}

// ---------------- HMMA GEMM + fused elu (+mean partials) ----------------
// out flow: v = acc + bias (+res); [x write if WRITE_X]; HE = elu(v);
//           [per-CTA column partials of elu(v)*mask if RED]
#define STRD 136
#define ASZ  (128 * STRD * 2)
#define SMTOT (4 * ASZ)

template <int NCH, bool ADD_RES, bool RED>
__global__ __launch_bounds__(256, 1)
void gemm_mma(const float* __restrict__ A1, const float* __restrict__ A2,
              const __nv_bfloat16* __restrict__ Wh, const __nv_bfloat16* __restrict__ Wl,
              const float* __restrict__ bias, const float* __restrict__ res,
              const float* __restrict__ mask,
              float* __restrict__ outx, float* __restrict__ outhe) {
    extern __shared__ char smem[];
    char* AH = smem;
    char* AL = smem + ASZ;
    const uint32_t sb = smem_u32(smem);

    const int tid = threadIdx.x;
    const int wid = tid >> 5, lane = tid & 31;
    const int wm = wid & 3, wn = wid >> 2;
    const int m0 = blockIdx.x * 128;
    const int gid = lane >> 2, tid4 = lane & 3;

    float acc[2][8][4] = {};

    const int frow = tid >> 1;
    const int fcol = (tid & 1) * 64;
    const bool rowok = (m0 + frow) < NN;

    const uint32_t aBase = sb +
        (uint32_t)(((wm * 32 + (lane & 15)) * STRD + (lane >> 4) * 8) * 2);
    const uint32_t bBase = sb + 2 * ASZ +
        (uint32_t)(((wn * 64 + (lane & 7) + ((lane >> 4) * 8)) * STRD + ((lane >> 3) & 1) * 8) * 2);

#pragma unroll
    for (int kc = 0; kc < NCH; kc++) {
        if (kc > 0) __syncthreads();
        // B staging via cp.async (overlaps with A conversion below)
        {
            uint32_t dh = sb + 2 * ASZ + (uint32_t)((frow * STRD + fcol) * 2);
            uint32_t dl = dh + ASZ;
            const char* gh = (const char*)(Wh + (size_t)frow * 256 + kc * 128 + fcol);
            const char* gl = (const char*)(Wl + (size_t)frow * 256 + kc * 128 + fcol);
#pragma unroll
            for (int q = 0; q < 8; q++) {
                cp16(dh + q * 16, gh + q * 16);
                cp16(dl + q * 16, gl + q * 16);
            }
        }
        // A staging: fp32 -> bf16 hi/lo
        {
            const float* Ag = (NCH == 2 && kc == 1) ? A2 : A1;
            const float* ap = Ag + (size_t)(m0 + frow) * CC + fcol;
            char* dh = AH + (frow * STRD + fcol) * 2;
            char* dl = AL + (frow * STRD + fcol) * 2;
#pragma unroll
            for (int q = 0; q < 16; q++) {
                float4 v = rowok ? *(const float4*)(ap + q * 4) : make_float4(0.f, 0.f, 0.f, 0.f);
                unsigned short hx = bfbits(v.x), hy = bfbits(v.y), hz = bfbits(v.z), hw = bfbits(v.w);
                float lx = v.x - __bfloat162float(__ushort_as_bfloat16(hx));
                float ly = v.y - __bfloat162float(__ushort_as_bfloat16(hy));
                float lz = v.z - __bfloat162float(__ushort_as_bfloat16(hz));
                float lw = v.w - __bfloat162float(__ushort_as_bfloat16(hw));
                *(uint2*)(dh + q * 8) =
                    make_uint2((uint32_t)hx | ((uint32_t)hy << 16), (uint32_t)hz | ((uint32_t)hw << 16));
                *(uint2*)(dl + q * 8) =
                    make_uint2((uint32_t)bfbits(lx) | ((uint32_t)bfbits(ly) << 16),
                               (uint32_t)bfbits(lz) | ((uint32_t)bfbits(lw) << 16));
            }
        }
        cp_wait();
        __syncthreads();

#pragma unroll
        for (int ks = 0; ks < 8; ks++) {
            uint32_t ah[2][4], al[2][4], bh[4][4], bl[4][4];
#pragma unroll
            for (int mf = 0; mf < 2; mf++) {
                uint32_t off = (uint32_t)((mf * 16 * STRD + ks * 16) * 2);
                ldsm_x4(ah[mf], aBase + off);
                ldsm_x4(al[mf], aBase + ASZ + off);
            }
#pragma unroll
            for (int nfp = 0; nfp < 4; nfp++) {
                uint32_t off = (uint32_t)((nfp * 16 * STRD + ks * 16) * 2);
                ldsm_x4(bh[nfp], bBase + off);
                ldsm_x4(bl[nfp], bBase + ASZ + off);
            }
#pragma unroll
            for (int mf = 0; mf < 2; mf++)
#pragma unroll
                for (int nfp = 0; nfp < 4; nfp++)
#pragma unroll
                    for (int h = 0; h < 2; h++) {
                        float* d = acc[mf][nfp * 2 + h];
                        mma16816(d, ah[mf], &bh[nfp][h * 2]);
                        mma16816(d, ah[mf], &bl[nfp][h * 2]);
                        mma16816(d, al[mf], &bh[nfp][h * 2]);
                    }
        }
    }

    // ---- epilogue: bias (+res), x write, elu->HE, optional partials ----
    float redv[16];
    float mval[2][2];
#pragma unroll
    for (int k = 0; k < 16; k++) redv[k] = 0.f;
    if (RED) {
#pragma unroll
        for (int mf = 0; mf < 2; mf++)
#pragma unroll
            for (int hh = 0; hh < 2; hh++) {
                int row = m0 + wm * 32 + mf * 16 + hh * 8 + gid;
                mval[mf][hh] = (row < NN) ? mask[row] : 0.f;
            }
    }

#pragma unroll
    for (int mf = 0; mf < 2; mf++) {
#pragma unroll
        for (int hh = 0; hh < 2; hh++) {
            int row = m0 + wm * 32 + mf * 16 + hh * 8 + gid;
            bool ok = row < NN;
#pragma unroll
            for (int nf = 0; nf < 8; nf++) {
                int col = wn * 64 + nf * 8 + tid4 * 2;
                float vx = acc[mf][nf][hh * 2 + 0] + bias[col];
                float vy = acc[mf][nf][hh * 2 + 1] + bias[col + 1];
                if (ADD_RES && ok) {
                    float2 rr = *(const float2*)&res[(size_t)row * CC + col];
                    vx += rr.x; vy += rr.y;
                }
                float hx = elu1(vx), hy = elu1(vy);
                if (ok) {
                    if (ADD_RES)
                        *(float2*)&outx[(size_t)row * CC + col] = make_float2(vx, vy);
                    *(float2*)&outhe[(size_t)row * CC + col] = make_float2(hx, hy);
                }
                if (RED) {
                    redv[nf * 2 + 0] += hx * mval[mf][hh];
                    redv[nf * 2 + 1] += hy * mval[mf][hh];
                }
            }
        }
    }

    if (RED) {
        // reduce over gid (rows within warp): lanes gid*4+tid4 -> gid==0
#pragma unroll
        for (int o = 16; o >= 4; o >>= 1)
#pragma unroll
            for (int k = 0; k < 16; k++)
                redv[k] += __shfl_down_sync(0xffffffffu, redv[k], o);
        __syncthreads();                 // smem (AH region) reuse safe after mainloop
        float* sred = (float*)smem;      // [4][128]
        if (lane < 4) {
#pragma unroll
            for (int nf = 0; nf < 8; nf++) {
                sred[wm * 128 + wn * 64 + nf * 8 + tid4 * 2 + 0] = redv[nf * 2 + 0];
                sred[wm * 128 + wn * 64 + nf * 8 + tid4 * 2 + 1] = redv[nf * 2 + 1];
            }
        }
        __syncthreads();
        if (tid < 128)
            g_partial[blockIdx.x * CC + tid] =
                sred[tid] + sred[128 + tid] + sred[256 + tid] + sred[384 + tid];
    }
}

// ---------------- final: out[n] = HE[n,:] . W2 + b2 + inputs[n,0] ----------------
__global__ void final_kernel(const float* __restrict__ HE, const float* __restrict__ W2,
                             const float* __restrict__ b2, const float* __restrict__ in,
                             float* __restrict__ out) {
    int warp = (blockIdx.x * blockDim.x + threadIdx.x) >> 5;
    int lane = threadIdx.x & 31;
    if (warp >= NN) return;
    float4 x = *(const float4*)&HE[(size_t)warp * CC + lane * 4];
    float4 w = *(const float4*)&W2[lane * 4];
    float s = x.x * w.x + x.y * w.y + x.z * w.z + x.w * w.w;
#pragma unroll
    for (int o = 16; o > 0; o >>= 1) s += __shfl_down_sync(0xffffffffu, s, o);
    if (lane == 0) out[warp] = s + b2[0] + in[warp * 3];
}

// ---------------- host launch ----------------
extern "C" void kernel_launch(void* const* d_in, const int* in_sizes, int n_in,
                              void* d_out, int out_size) {
    const int*   L_row  = (const int*)d_in[0];
    const int*   L_col  = (const int*)d_in[1];
    const float* L_val  = (const float*)d_in[2];
    const float* mask   = (const float*)d_in[3];
    const float* inputs = (const float*)d_in[4];
    const float* W1     = (const float*)d_in[5];
    const float* b1     = (const float*)d_in[6];
    const float* BW     = (const float*)d_in[7];
    const float* Bb     = (const float*)d_in[8];
    const float* W2     = (const float*)d_in[9];
    const float* b2     = (const float*)d_in[10];
    float* out = (float*)d_out;

    float *B0, *HE, *P, *cvec;
    __nv_bfloat16 *Wh, *Wl;
    cudaGetSymbolAddress((void**)&B0, g_B0);
    cudaGetSymbolAddress((void**)&HE, g_HE);
    cudaGetSymbolAddress((void**)&P,  g_P);
    cudaGetSymbolAddress((void**)&cvec, g_cvec);
    cudaGetSymbolAddress((void**)&Wh, g_Wh);
    cudaGetSymbolAddress((void**)&Wl, g_Wl);

    static bool attr_done = false;
    if (!attr_done) {
        cudaFuncSetAttribute(gemm_mma<2, false, false>, cudaFuncAttributeMaxDynamicSharedMemorySize, SMTOT);
        cudaFuncSetAttribute(gemm_mma<2, true,  true>,  cudaFuncAttributeMaxDynamicSharedMemorySize, SMTOT);
        cudaFuncSetAttribute(gemm_mma<2, true,  false>, cudaFuncAttributeMaxDynamicSharedMemorySize, SMTOT);
        cudaFuncSetAttribute(gemm_mma<1, false, true>,  cudaFuncAttributeMaxDynamicSharedMemorySize, SMTOT);
        cudaFuncSetAttribute(gemm_mma<1, true,  false>, cudaFuncAttributeMaxDynamicSharedMemorySize, SMTOT);
        attr_done = true;
    }

    // ---- setup (per replay) ----
    zero2_kernel<<<(NN + 255) / 256, 256>>>();
    hist_kernel<<<(NE + 255) / 256, 256>>>(L_row);
    scan1_kernel<<<SCAN_NCHUNK, SCAN_CHUNK>>>();
    scan23_kernel<<<SCAN_NCHUNK, SCAN_CHUNK>>>();
    fill_kernel<<<(NE + 255) / 256, 256>>>(L_row, L_col, L_val);
    masksum_kernel<<<1, 1024>>>(mask);
    wprep_kernel<<<(NSTEPS * 128 * 256 + 255) / 256, 256>>>(BW);

    conv1_kernel<<<(NN * CC + 255) / 256, 256>>>(inputs, W1, b1, B0, HE);

    const int LAP_GRID = (NN * 32 + 255) / 256;

    for (int i = 0; i < NLAYERS; i++) {
        for (int j = 0; j < 2; j++) {
            int step = i * 2 + j;
            const __nv_bfloat16* Whs = Wh + (size_t)step * 128 * 256;
            const __nv_bfloat16* Wls = Wl + (size_t)step * 128 * 256;
            const float* b = Bb + (size_t)step * CC;
            bool last = (step == NSTEPS - 1);

            if ((i & 1) == 0) {
                // lap layer: HE holds elu of this step's input already
                lap_kernel<<<LAP_GRID, 256>>>(HE, P);
                if (j == 0)
                    // next consumer is same (even) layer -> no partials
                    gemm_mma<2, false, false><<<GGRID, 256, SMTOT>>>(
                        HE, P, Whs, Wls, b, nullptr, mask, nullptr, HE);
                else if (!last)
                    // next layer i+1 is odd -> partials needed
                    gemm_mma<2, true, true><<<GGRID, 256, SMTOT>>>(
                        HE, P, Whs, Wls, b, B0, mask, B0, HE);
                else
                    gemm_mma<2, true, false><<<GGRID, 256, SMTOT>>>(
                        HE, P, Whs, Wls, b, B0, mask, B0, HE);
            } else {
                // mean layer: partials were produced by previous gemm
                cvec_kernel<<<1, CC>>>(BW + (size_t)step * 256 * CC + 128 * CC, b);
                if (j == 0)
                    // next consumer same odd layer -> partials needed
                    gemm_mma<1, false, true><<<GGRID, 256, SMTOT>>>(
                        HE, nullptr, Whs, Wls, cvec, nullptr, mask, nullptr, HE);
                else
                    // next layer even -> no partials
                    gemm_mma<1, true, false><<<GGRID, 256, SMTOT>>>(
                        HE, nullptr, Whs, Wls, cvec, B0, mask, B0, HE);
            }
        }
    }

    final_kernel<<<(NN * 32 + 1023) / 1024, 1024>>>(HE, W2, b2, inputs, out);

    (void)in_sizes; (void)n_in; (void)out_size;
}